// round 16
// baseline (speedup 1.0000x reference)
#include <cuda_runtime.h>
#include <cuda_fp16.h>
#include <cstdint>

// ============================================================================
// Scratch (static __device__ arrays — no allocations allowed)
// ============================================================================
#define KROWS 8192
#define NROWS 8192
#define MDIM  64
#define TI    128
#define TJ    128
#define NTILES 4096         // 64 i-tiles x 64 j-tiles
#define GRID_MAIN 296       // 148 SMs x 2 CTAs

__device__ __half g_Xh[KROWS * MDIM];       // x in f16
__device__ __half g_Ch[NROWS * MDIM];       // x_basis in f16
__device__ __half g_xsh[KROWS];             // -log2e * ||x_i||^2  (f16)
__device__ __half g_csh[NROWS];             // -log2e * ||c_j||^2  (f16)
__device__ __half g_wh[NROWS];              // w_j                 (f16)
__device__ float  g_logit[KROWS];           // accumulated logits (prep zeroes)

#define LOG2E 1.4426950408889634f

// ============================================================================
// PTX helpers (baseline features only — sm_100 non-'a' target)
// ============================================================================
__device__ __forceinline__ uint32_t smem_u32(const void* p) {
    uint32_t a;
    asm("{ .reg .u64 t; cvta.to.shared.u64 t, %1; cvt.u32.u64 %0, t; }"
        : "=r"(a) : "l"(p));
    return a;
}

// f16 x f16 -> f16 accumulate
__device__ __forceinline__ void mma16816_f16(uint32_t& c0, uint32_t& c1,
                                             const uint32_t* a,
                                             uint32_t b0, uint32_t b1) {
    asm volatile(
        "mma.sync.aligned.m16n8k16.row.col.f16.f16.f16.f16 "
        "{%0,%1}, {%2,%3,%4,%5}, {%6,%7}, {%0,%1};"
        : "+r"(c0), "+r"(c1)
        : "r"(a[0]), "r"(a[1]), "r"(a[2]), "r"(a[3]), "r"(b0), "r"(b1));
}

__device__ __forceinline__ void ldsm_x4(uint32_t addr, uint32_t* r) {
    asm volatile("ldmatrix.sync.aligned.m8n8.x4.shared.b16 {%0,%1,%2,%3}, [%4];"
                 : "=r"(r[0]), "=r"(r[1]), "=r"(r[2]), "=r"(r[3]) : "r"(addr));
}

#define CP_ASYNC16(dst, src) \
    asm volatile("cp.async.cg.shared.global [%0], [%1], 16;" :: "r"(dst), "l"(src))
#define CP_COMMIT() asm volatile("cp.async.commit_group;" ::: "memory")
#define CP_WAIT0()  asm volatile("cp.async.wait_group 0;" ::: "memory")

__device__ __forceinline__ uint32_t ex2_h2(uint32_t t) {
    uint32_t e;
    asm("ex2.approx.f16x2 %0, %1;" : "=r"(e) : "r"(t));
    return e;
}

// ============================================================================
// K1: convert to f16, norms, cs/w pack; zero the logit accumulator
// 512 blocks x 256 threads; 8 threads/row, 2 independent float4 each (MLP=2)
// ============================================================================
__global__ void prep_kernel(const float* __restrict__ x,
                            const float* __restrict__ xb,
                            const float* __restrict__ w) {
    int idx  = blockIdx.x * 256 + threadIdx.x;
    if (idx < KROWS) g_logit[idx] = 0.0f;   // reset accumulators each launch
    int row8 = idx >> 3;                    // 0..16383
    int s    = idx & 7;
    bool isb = row8 >= KROWS;
    int r    = isb ? row8 - KROWS : row8;
    const float* src = isb ? xb : x;

    const float4* rp = (const float4*)(src + (size_t)r * MDIM);
    float4 v0 = rp[s];
    float4 v1 = rp[s + 8];

    __half2 a01 = __floats2half2_rn(v0.x, v0.y);
    __half2 a23 = __floats2half2_rn(v0.z, v0.w);
    __half2 b01 = __floats2half2_rn(v1.x, v1.y);
    __half2 b23 = __floats2half2_rn(v1.z, v1.w);
    __half* dst = isb ? g_Ch : g_Xh;
    uint2* dp = (uint2*)(dst + (size_t)r * MDIM);
    uint2 p0, p1;
    p0.x = *(const uint32_t*)&a01; p0.y = *(const uint32_t*)&a23;
    p1.x = *(const uint32_t*)&b01; p1.y = *(const uint32_t*)&b23;
    dp[s]     = p0;
    dp[s + 8] = p1;

    float nrm = v0.x * v0.x + v0.y * v0.y + v0.z * v0.z + v0.w * v0.w
              + v1.x * v1.x + v1.y * v1.y + v1.z * v1.z + v1.w * v1.w;
    #pragma unroll
    for (int o = 4; o; o >>= 1) nrm += __shfl_xor_sync(0xFFFFFFFFu, nrm, o);

    if (s == 0) {
        float e = -LOG2E * nrm;
        if (isb) {
            g_csh[r] = __float2half(e);
            g_wh[r]  = __float2half(w[r]);
        } else {
            g_xsh[r] = __float2half(e);
        }
    }
}

// ============================================================================
// K2: statically balanced f16 GEMM + fused exp/weighted-sum epilogue
// grid = 296 CTAs (2/SM), 256 threads = 8 warps (4 warp-rows x 2 cols)
// B fragments register double-buffered across k-steps AND across tile
// boundaries: the next tile's first ldsm hides under this tile's half-1
// epilogue. CTA b owns contiguous i-major tile range [b*4096/296, ...).
// ============================================================================
#define TILE_BYTES 16384    // 128 rows x 128 B (64 f16)

__device__ __forceinline__ void stage_tile(uint32_t sdst,
                                           const __half* gsrc, int tid) {
    #pragma unroll
    for (int p = 0; p < 4; p++) {
        int c   = tid + (p << 8);            // 0..1023 16B-chunks
        int row = c >> 3, ch = c & 7;
        uint32_t dst = sdst + (row << 7) + ((ch ^ (row & 7)) << 4);
        const char* src = (const char*)gsrc + (row << 7) + (ch << 4);
        CP_ASYNC16(dst, src);
    }
}

// load one half's 4 n-octet B fragments for k-step chunk ch
__device__ __forceinline__ void load_bfr(uint32_t sb, int rowbase, int ch,
                                         uint32_t bfr[4][2]) {
    #pragma unroll
    for (int ga = 0; ga < 2; ga++) {
        int row = rowbase + ga * 16;
        uint32_t r[4];
        ldsm_x4(sb + (row << 7) + ((ch ^ (row & 7)) << 4), r);
        bfr[ga * 2 + 0][0] = r[0]; bfr[ga * 2 + 0][1] = r[1];
        bfr[ga * 2 + 1][0] = r[2]; bfr[ga * 2 + 1][1] = r[3];
    }
}

__device__ __forceinline__ void extract_A(uint32_t sA, int i0, int wrow,
                                          int lid, int g,
                                          uint32_t a[2][4][4], uint32_t xsb[2][2]) {
    const int arow_lo = (lid & 7) + ((lid >> 3) & 1) * 8;
    const int chsel   = lid >> 4;
    #pragma unroll
    for (int mt = 0; mt < 2; mt++) {
        #pragma unroll
        for (int ks = 0; ks < 4; ks++) {
            int row = wrow * 32 + mt * 16 + arow_lo;
            int ch  = ks * 2 + chsel;
            ldsm_x4(sA + (row << 7) + ((ch ^ (row & 7)) << 4), a[mt][ks]);
        }
    }
    #pragma unroll
    for (int mt = 0; mt < 2; mt++)
        #pragma unroll
        for (int h = 0; h < 2; h++) {
            __half2 b2 = __half2half2(g_xsh[i0 + wrow * 32 + mt * 16 + g + h * 8]);
            xsb[mt][h] = *(const uint32_t*)&b2;
        }
}

__device__ __forceinline__ void flush_acc(__half2 acc2[2][2], int i0, int wrow,
                                          int lid, int g) {
    #pragma unroll
    for (int mt = 0; mt < 2; mt++)
        #pragma unroll
        for (int h = 0; h < 2; h++) {
            float v = __low2float(acc2[mt][h]) + __high2float(acc2[mt][h]);
            v += __shfl_xor_sync(0xFFFFFFFFu, v, 1);
            v += __shfl_xor_sync(0xFFFFFFFFu, v, 2);
            if ((lid & 3) == 0)
                atomicAdd(&g_logit[i0 + wrow * 32 + mt * 16 + g + h * 8], v);
        }
}

__global__ void __launch_bounds__(256, 2) rbf_main_kernel() {
    __shared__ __align__(1024) uint8_t smA[TILE_BYTES];       // 16 KB
    __shared__ __align__(1024) uint8_t smB[2][TILE_BYTES];    // 32 KB

    const int tid = threadIdx.x;
    const int wid = tid >> 5;
    const int lid = tid & 31;
    const int wrow = wid >> 1;           // 0..3 (32-row slice of A)
    const int wc   = wid & 1;            // 0..1 (64-col slice of B)
    const int g    = lid >> 2;           // 0..7
    const int q2   = (lid & 3) * 2;      // 0,2,4,6

    const int b  = blockIdx.x;
    const int t0 = (b * NTILES) / GRID_MAIN;
    const int t1 = ((b + 1) * NTILES) / GRID_MAIN;

    const uint32_t sA  = smem_u32(smA);
    const uint32_t sB0 = smem_u32(smB[0]);
    const uint32_t sB1 = smem_u32(smB[1]);

    int it = t0 >> 6;
    // ---- prologue: stage A(it) and B(jt0) ----
    stage_tile(sA, g_Xh + (size_t)(it * TI) * MDIM, tid);
    stage_tile((t0 & 1) ? sB1 : sB0,
               g_Ch + (size_t)((t0 & 63) * TJ) * MDIM, tid);
    CP_COMMIT();
    CP_WAIT0();
    __syncthreads();

    uint32_t a[2][4][4];
    uint32_t xsb[2][2];
    extract_A(sA, it * TI, wrow, lid, g, a, xsb);
    __syncthreads();                     // extraction done before smA reuse

    const __half2 C2h = __float2half2_rn(2.0f * LOG2E);
    const uint32_t C2u = *(const uint32_t*)&C2h;

    __half2 acc2[2][2];
    #pragma unroll
    for (int mt = 0; mt < 2; mt++)
        #pragma unroll
        for (int h = 0; h < 2; h++) acc2[mt][h] = __float2half2_rn(0.f);

    // B-ldmatrix lane addressing: matrix m = lid>>3, row-octet (m>>1)
    const int brow_lo = wc * 64 + ((lid >> 4) << 3) + (lid & 7);
    const int bch_lo  = (lid >> 3) & 1;

    uint32_t bfr[2][4][2];
    // preload half0/ks0 of the first tile
    load_bfr((t0 & 1) ? sB1 : sB0, brow_lo, bch_lo, bfr[0]);

    for (int t = t0; t < t1; t++) {
        const int jt  = t & 63;
        const bool hn = (t + 1 < t1);
        const int nit = (t + 1) >> 6;

        if (hn) {   // prefetch next B (and next A at i-boundaries)
            stage_tile(((t + 1) & 1) ? sB1 : sB0,
                       g_Ch + (size_t)(((t + 1) & 63) * TJ) * MDIM, tid);
            if (nit != it)
                stage_tile(sA, g_Xh + (size_t)(nit * TI) * MDIM, tid);
            CP_COMMIT();
        }
        const uint32_t sb  = (t & 1) ? sB1 : sB0;
        const uint32_t sbn = (t & 1) ? sB0 : sB1;
        const int j0 = jt * TJ + wc * 64;

        // ================= half 0: MMA (pipelined) + epilogue ==============
        uint32_t c0[2][4][2];
        #pragma unroll
        for (int mt = 0; mt < 2; mt++)
            #pragma unroll
            for (int nt = 0; nt < 4; nt++) { c0[mt][nt][0] = 0u; c0[mt][nt][1] = 0u; }

        #pragma unroll
        for (int ks = 0; ks < 4; ks++) {
            const int cur = ks & 1, nxt = cur ^ 1;
            if (ks < 3)
                load_bfr(sb, brow_lo, (ks + 1) * 2 + bch_lo, bfr[nxt]);
            else
                load_bfr(sb, brow_lo + 32, bch_lo, bfr[nxt]);   // half1, ks0
            #pragma unroll
            for (int nt = 0; nt < 4; nt++) {
                mma16816_f16(c0[0][nt][0], c0[0][nt][1], a[0][ks],
                             bfr[cur][nt][0], bfr[cur][nt][1]);
                mma16816_f16(c0[1][nt][0], c0[1][nt][1], a[1][ks],
                             bfr[cur][nt][0], bfr[cur][nt][1]);
            }
        }

        #pragma unroll
        for (int nt = 0; nt < 4; nt++) {
            const int jj = j0 + nt * 8 + q2;
            const uint32_t cs2 = *(const uint32_t*)(g_csh + jj);
            const uint32_t w2  = *(const uint32_t*)(g_wh + jj);
            const __half2 cs2h = *(const __half2*)&cs2;
            const __half2 w2h  = *(const __half2*)&w2;
            #pragma unroll
            for (int mt = 0; mt < 2; mt++)
                #pragma unroll
                for (int h = 0; h < 2; h++) {
                    __half2 base = __hadd2(*(const __half2*)&xsb[mt][h], cs2h);
                    __half2 cc   = *(const __half2*)&c0[mt][nt][h];
                    __half2 t2   = __hfma2(cc, *(const __half2*)&C2u, base);
                    uint32_t e   = ex2_h2(*(const uint32_t*)&t2);
                    acc2[mt][h]  = __hfma2(*(const __half2*)&e, w2h, acc2[mt][h]);
                }
        }

        // ================= half 1: MMA (pipelined) =========================
        uint32_t c1[2][4][2];
        #pragma unroll
        for (int mt = 0; mt < 2; mt++)
            #pragma unroll
            for (int nt = 0; nt < 4; nt++) { c1[mt][nt][0] = 0u; c1[mt][nt][1] = 0u; }

        #pragma unroll
        for (int ks = 0; ks < 4; ks++) {
            const int cur = ks & 1, nxt = cur ^ 1;
            if (ks < 3)
                load_bfr(sb, brow_lo + 32, (ks + 1) * 2 + bch_lo, bfr[nxt]);
            #pragma unroll
            for (int nt = 0; nt < 4; nt++) {
                mma16816_f16(c1[0][nt][0], c1[0][nt][1], a[0][ks],
                             bfr[cur][nt][0], bfr[cur][nt][1]);
                mma16816_f16(c1[1][nt][0], c1[1][nt][1], a[1][ks],
                             bfr[cur][nt][0], bfr[cur][nt][1]);
            }
        }

        // ---- next B buffer ready; preload next tile's half0/ks0 so the
        //      cross-tile ldsm hides under the half-1 epilogue below ----
        if (hn) {
            CP_WAIT0();
            __syncthreads();
            load_bfr(sbn, brow_lo, bch_lo, bfr[0]);
        }

        // ================= half 1 epilogue =================================
        #pragma unroll
        for (int nt = 0; nt < 4; nt++) {
            const int jj = j0 + 32 + nt * 8 + q2;
            const uint32_t cs2 = *(const uint32_t*)(g_csh + jj);
            const uint32_t w2  = *(const uint32_t*)(g_wh + jj);
            const __half2 cs2h = *(const __half2*)&cs2;
            const __half2 w2h  = *(const __half2*)&w2;
            #pragma unroll
            for (int mt = 0; mt < 2; mt++)
                #pragma unroll
                for (int h = 0; h < 2; h++) {
                    __half2 base = __hadd2(*(const __half2*)&xsb[mt][h], cs2h);
                    __half2 cc   = *(const __half2*)&c1[mt][nt][h];
                    __half2 t2   = __hfma2(cc, *(const __half2*)&C2u, base);
                    uint32_t e   = ex2_h2(*(const uint32_t*)&t2);
                    acc2[mt][h]  = __hfma2(*(const __half2*)&e, w2h, acc2[mt][h]);
                }
        }

        if (hn && nit != it) {
            // i-segment boundary: flush rows, pick up the new A (already staged)
            flush_acc(acc2, it * TI, wrow, lid, g);
            it = nit;
            extract_A(sA, it * TI, wrow, lid, g, a, xsb);
            __syncthreads();             // extraction done before smA reuse
            #pragma unroll
            for (int mt = 0; mt < 2; mt++)
                #pragma unroll
                for (int h = 0; h < 2; h++) acc2[mt][h] = __float2half2_rn(0.f);
        }
    }

    flush_acc(acc2, it * TI, wrow, lid, g);
}

// ============================================================================
// K3: bias + sigmoid
// ============================================================================
__global__ void finish_kernel(const float* __restrict__ b, float* __restrict__ out) {
    int i = blockIdx.x * 256 + threadIdx.x;
    float z = g_logit[i] + b[0];
    out[i] = 1.0f / (1.0f + __expf(-z));
}

// ============================================================================
// kernel_launch
// ============================================================================
extern "C" void kernel_launch(void* const* d_in, const int* in_sizes, int n_in,
                              void* d_out, int out_size) {
    const float* x  = (const float*)d_in[0];
    const float* xb = (const float*)d_in[1];
    const float* w  = (const float*)d_in[2];
    const float* b  = (const float*)d_in[3];
    float* out = (float*)d_out;

    prep_kernel<<<512, 256>>>(x, xb, w);
    rbf_main_kernel<<<GRID_MAIN, 256>>>();
    finish_kernel<<<KROWS / 256, 256>>>(b, out);
}

// round 17
// speedup vs baseline: 1.0555x; 1.0555x over previous
#include <cuda_runtime.h>
#include <cuda_fp16.h>
#include <cstdint>

// ============================================================================
// Scratch (static __device__ arrays — no allocations allowed)
// ============================================================================
#define KROWS 8192
#define NROWS 8192
#define MDIM  64
#define TI    128
#define TJ    128
#define NTILES 4096         // 64 i-tiles x 64 j-tiles
#define GRID_MAIN 296       // 148 SMs x 2 CTAs

__device__ __half g_Xh[KROWS * MDIM];       // x in f16
__device__ __half g_Ch[NROWS * MDIM];       // x_basis in f16
__device__ __half g_xsh[KROWS];             // -log2e * ||x_i||^2  (f16)
__device__ __half g_csh[NROWS];             // -log2e * ||c_j||^2  (f16)
__device__ __half g_wh[NROWS];              // w_j                 (f16)
__device__ float  g_logit[KROWS];           // accumulated logits (prep zeroes)

#define LOG2E 1.4426950408889634f

// ============================================================================
// PTX helpers (baseline features only — sm_100 non-'a' target)
// ============================================================================
__device__ __forceinline__ uint32_t smem_u32(const void* p) {
    uint32_t a;
    asm("{ .reg .u64 t; cvta.to.shared.u64 t, %1; cvt.u32.u64 %0, t; }"
        : "=r"(a) : "l"(p));
    return a;
}

// f16 x f16 -> f16 accumulate
__device__ __forceinline__ void mma16816_f16(uint32_t& c0, uint32_t& c1,
                                             const uint32_t* a,
                                             uint32_t b0, uint32_t b1) {
    asm volatile(
        "mma.sync.aligned.m16n8k16.row.col.f16.f16.f16.f16 "
        "{%0,%1}, {%2,%3,%4,%5}, {%6,%7}, {%0,%1};"
        : "+r"(c0), "+r"(c1)
        : "r"(a[0]), "r"(a[1]), "r"(a[2]), "r"(a[3]), "r"(b0), "r"(b1));
}

__device__ __forceinline__ void ldsm_x4(uint32_t addr, uint32_t* r) {
    asm volatile("ldmatrix.sync.aligned.m8n8.x4.shared.b16 {%0,%1,%2,%3}, [%4];"
                 : "=r"(r[0]), "=r"(r[1]), "=r"(r[2]), "=r"(r[3]) : "r"(addr));
}

#define CP_ASYNC16(dst, src) \
    asm volatile("cp.async.cg.shared.global [%0], [%1], 16;" :: "r"(dst), "l"(src))
#define CP_COMMIT() asm volatile("cp.async.commit_group;" ::: "memory")
#define CP_WAIT0()  asm volatile("cp.async.wait_group 0;" ::: "memory")

__device__ __forceinline__ uint32_t ex2_h2(uint32_t t) {
    uint32_t e;
    asm("ex2.approx.f16x2 %0, %1;" : "=r"(e) : "r"(t));
    return e;
}

// ============================================================================
// K1: convert to f16, norms, cs/w pack; zero the logit accumulator
// 512 blocks x 256 threads; 8 threads/row, 2 independent float4 each (MLP=2)
// ============================================================================
__global__ void prep_kernel(const float* __restrict__ x,
                            const float* __restrict__ xb,
                            const float* __restrict__ w) {
    int idx  = blockIdx.x * 256 + threadIdx.x;
    if (idx < KROWS) g_logit[idx] = 0.0f;   // reset accumulators each launch
    int row8 = idx >> 3;                    // 0..16383
    int s    = idx & 7;
    bool isb = row8 >= KROWS;
    int r    = isb ? row8 - KROWS : row8;
    const float* src = isb ? xb : x;

    const float4* rp = (const float4*)(src + (size_t)r * MDIM);
    float4 v0 = rp[s];
    float4 v1 = rp[s + 8];

    __half2 a01 = __floats2half2_rn(v0.x, v0.y);
    __half2 a23 = __floats2half2_rn(v0.z, v0.w);
    __half2 b01 = __floats2half2_rn(v1.x, v1.y);
    __half2 b23 = __floats2half2_rn(v1.z, v1.w);
    __half* dst = isb ? g_Ch : g_Xh;
    uint2* dp = (uint2*)(dst + (size_t)r * MDIM);
    uint2 p0, p1;
    p0.x = *(const uint32_t*)&a01; p0.y = *(const uint32_t*)&a23;
    p1.x = *(const uint32_t*)&b01; p1.y = *(const uint32_t*)&b23;
    dp[s]     = p0;
    dp[s + 8] = p1;

    float nrm = v0.x * v0.x + v0.y * v0.y + v0.z * v0.z + v0.w * v0.w
              + v1.x * v1.x + v1.y * v1.y + v1.z * v1.z + v1.w * v1.w;
    #pragma unroll
    for (int o = 4; o; o >>= 1) nrm += __shfl_xor_sync(0xFFFFFFFFu, nrm, o);

    if (s == 0) {
        float e = -LOG2E * nrm;
        if (isb) {
            g_csh[r] = __float2half(e);
            g_wh[r]  = __float2half(w[r]);
        } else {
            g_xsh[r] = __float2half(e);
        }
    }
}

// ============================================================================
// K2: statically balanced f16 GEMM + fused exp/weighted-sum epilogue
// grid = 296 CTAs (2/SM), 256 threads = 8 warps (4 warp-rows x 2 cols)
// R15 structure (barrier at tile END) + cs/w register prefetch at tile top.
// B fragments register double-buffered across k-steps; half-0 epilogue
// overlaps half-1's first fragment loads.
// CTA b owns contiguous i-major tile range [b*4096/296, (b+1)*4096/296).
// ============================================================================
#define TILE_BYTES 16384    // 128 rows x 128 B (64 f16)

__device__ __forceinline__ void stage_tile(uint32_t sdst,
                                           const __half* gsrc, int tid) {
    #pragma unroll
    for (int p = 0; p < 4; p++) {
        int c   = tid + (p << 8);            // 0..1023 16B-chunks
        int row = c >> 3, ch = c & 7;
        uint32_t dst = sdst + (row << 7) + ((ch ^ (row & 7)) << 4);
        const char* src = (const char*)gsrc + (row << 7) + (ch << 4);
        CP_ASYNC16(dst, src);
    }
}

// load one half's 4 n-octet B fragments for k-step chunk ch
__device__ __forceinline__ void load_bfr(uint32_t sb, int rowbase, int ch,
                                         uint32_t bfr[4][2]) {
    #pragma unroll
    for (int ga = 0; ga < 2; ga++) {
        int row = rowbase + ga * 16;
        uint32_t r[4];
        ldsm_x4(sb + (row << 7) + ((ch ^ (row & 7)) << 4), r);
        bfr[ga * 2 + 0][0] = r[0]; bfr[ga * 2 + 0][1] = r[1];
        bfr[ga * 2 + 1][0] = r[2]; bfr[ga * 2 + 1][1] = r[3];
    }
}

__device__ __forceinline__ void extract_A(uint32_t sA, int i0, int wrow,
                                          int lid, int g,
                                          uint32_t a[2][4][4], uint32_t xsb[2][2]) {
    const int arow_lo = (lid & 7) + ((lid >> 3) & 1) * 8;
    const int chsel   = lid >> 4;
    #pragma unroll
    for (int mt = 0; mt < 2; mt++) {
        #pragma unroll
        for (int ks = 0; ks < 4; ks++) {
            int row = wrow * 32 + mt * 16 + arow_lo;
            int ch  = ks * 2 + chsel;
            ldsm_x4(sA + (row << 7) + ((ch ^ (row & 7)) << 4), a[mt][ks]);
        }
    }
    #pragma unroll
    for (int mt = 0; mt < 2; mt++)
        #pragma unroll
        for (int h = 0; h < 2; h++) {
            __half2 b2 = __half2half2(g_xsh[i0 + wrow * 32 + mt * 16 + g + h * 8]);
            xsb[mt][h] = *(const uint32_t*)&b2;
        }
}

__device__ __forceinline__ void flush_acc(__half2 acc2[2][2], int i0, int wrow,
                                          int lid, int g) {
    #pragma unroll
    for (int mt = 0; mt < 2; mt++)
        #pragma unroll
        for (int h = 0; h < 2; h++) {
            float v = __low2float(acc2[mt][h]) + __high2float(acc2[mt][h]);
            v += __shfl_xor_sync(0xFFFFFFFFu, v, 1);
            v += __shfl_xor_sync(0xFFFFFFFFu, v, 2);
            if ((lid & 3) == 0)
                atomicAdd(&g_logit[i0 + wrow * 32 + mt * 16 + g + h * 8], v);
        }
}

__global__ void __launch_bounds__(256, 2) rbf_main_kernel() {
    __shared__ __align__(1024) uint8_t smA[TILE_BYTES];       // 16 KB
    __shared__ __align__(1024) uint8_t smB[2][TILE_BYTES];    // 32 KB

    const int tid = threadIdx.x;
    const int wid = tid >> 5;
    const int lid = tid & 31;
    const int wrow = wid >> 1;           // 0..3 (32-row slice of A)
    const int wc   = wid & 1;            // 0..1 (64-col slice of B)
    const int g    = lid >> 2;           // 0..7
    const int q2   = (lid & 3) * 2;      // 0,2,4,6

    const int b  = blockIdx.x;
    const int t0 = (b * NTILES) / GRID_MAIN;
    const int t1 = ((b + 1) * NTILES) / GRID_MAIN;

    const uint32_t sA  = smem_u32(smA);
    const uint32_t sB0 = smem_u32(smB[0]);
    const uint32_t sB1 = smem_u32(smB[1]);

    int it = t0 >> 6;
    // ---- prologue: stage A(it) and B(jt0) ----
    stage_tile(sA, g_Xh + (size_t)(it * TI) * MDIM, tid);
    stage_tile((t0 & 1) ? sB1 : sB0,
               g_Ch + (size_t)((t0 & 63) * TJ) * MDIM, tid);
    CP_COMMIT();
    CP_WAIT0();
    __syncthreads();

    uint32_t a[2][4][4];
    uint32_t xsb[2][2];
    extract_A(sA, it * TI, wrow, lid, g, a, xsb);
    __syncthreads();                     // extraction done before smA reuse

    const __half2 C2h = __float2half2_rn(2.0f * LOG2E);
    const uint32_t C2u = *(const uint32_t*)&C2h;

    __half2 acc2[2][2];
    #pragma unroll
    for (int mt = 0; mt < 2; mt++)
        #pragma unroll
        for (int h = 0; h < 2; h++) acc2[mt][h] = __float2half2_rn(0.f);

    // B-ldmatrix lane addressing: matrix m = lid>>3, row-octet (m>>1)
    const int brow_lo = wc * 64 + ((lid >> 4) << 3) + (lid & 7);
    const int bch_lo  = (lid >> 3) & 1;

    for (int t = t0; t < t1; t++) {
        const int jt  = t & 63;
        const bool hn = (t + 1 < t1);
        const int nit = (t + 1) >> 6;

        if (hn) {   // prefetch next B (and next A at i-boundaries)
            stage_tile(((t + 1) & 1) ? sB1 : sB0,
                       g_Ch + (size_t)(((t + 1) & 63) * TJ) * MDIM, tid);
            if (nit != it)
                stage_tile(sA, g_Xh + (size_t)(nit * TI) * MDIM, tid);
            CP_COMMIT();
        }
        const uint32_t sb = (t & 1) ? sB1 : sB0;
        const int j0 = jt * TJ + wc * 64;

        // ---- cs/w register prefetch for the whole tile (8 col-octets):
        //      long-latency LDGs issue first, land under half-0 LDSM/MMA ----
        uint32_t csv[8], wv[8];
        #pragma unroll
        for (int nt = 0; nt < 8; nt++) {
            const int jj = j0 + nt * 8 + q2;
            csv[nt] = *(const uint32_t*)(g_csh + jj);
            wv[nt]  = *(const uint32_t*)(g_wh + jj);
        }

        // ---- software-pipelined B fragments across k-steps ----
        uint32_t bfr[2][4][2];
        load_bfr(sb, brow_lo, bch_lo, bfr[0]);          // half0, ks0

        #pragma unroll
        for (int half = 0; half < 2; half++) {
            uint32_t c[2][4][2];
            #pragma unroll
            for (int mt = 0; mt < 2; mt++)
                #pragma unroll
                for (int nt = 0; nt < 4; nt++) { c[mt][nt][0] = 0u; c[mt][nt][1] = 0u; }

            #pragma unroll
            for (int ks = 0; ks < 4; ks++) {
                const int cur = ks & 1, nxt = cur ^ 1;
                if (ks < 3)
                    load_bfr(sb, brow_lo + half * 32, (ks + 1) * 2 + bch_lo,
                             bfr[nxt]);
                else if (half == 0)
                    load_bfr(sb, brow_lo + 32, bch_lo, bfr[nxt]);  // half1, ks0
                #pragma unroll
                for (int nt = 0; nt < 4; nt++) {
                    mma16816_f16(c[0][nt][0], c[0][nt][1], a[0][ks],
                                 bfr[cur][nt][0], bfr[cur][nt][1]);
                    mma16816_f16(c[1][nt][0], c[1][nt][1], a[1][ks],
                                 bfr[cur][nt][0], bfr[cur][nt][1]);
                }
            }

            // epilogue for this half's 4 col-octets (registers only)
            #pragma unroll
            for (int nt = 0; nt < 4; nt++) {
                const __half2 cs2h = *(const __half2*)&csv[half * 4 + nt];
                const __half2 w2h  = *(const __half2*)&wv[half * 4 + nt];
                #pragma unroll
                for (int mt = 0; mt < 2; mt++) {
                    #pragma unroll
                    for (int h = 0; h < 2; h++) {
                        __half2 base = __hadd2(*(const __half2*)&xsb[mt][h], cs2h);
                        __half2 cc   = *(const __half2*)&c[mt][nt][h];
                        __half2 t2   = __hfma2(cc, *(const __half2*)&C2u, base);
                        uint32_t e   = ex2_h2(*(const uint32_t*)&t2);
                        acc2[mt][h]  = __hfma2(*(const __half2*)&e, w2h, acc2[mt][h]);
                    }
                }
            }
        }

        if (hn) CP_WAIT0();
        __syncthreads();

        if (hn && nit != it) {
            // i-segment boundary: flush rows, pick up the new A (already staged)
            flush_acc(acc2, it * TI, wrow, lid, g);
            it = nit;
            extract_A(sA, it * TI, wrow, lid, g, a, xsb);
            __syncthreads();             // extraction done before smA reuse
            #pragma unroll
            for (int mt = 0; mt < 2; mt++)
                #pragma unroll
                for (int h = 0; h < 2; h++) acc2[mt][h] = __float2half2_rn(0.f);
        }
    }

    flush_acc(acc2, it * TI, wrow, lid, g);
}

// ============================================================================
// K3: bias + sigmoid
// ============================================================================
__global__ void finish_kernel(const float* __restrict__ b, float* __restrict__ out) {
    int i = blockIdx.x * 256 + threadIdx.x;
    float z = g_logit[i] + b[0];
    out[i] = 1.0f / (1.0f + __expf(-z));
}

// ============================================================================
// kernel_launch
// ============================================================================
extern "C" void kernel_launch(void* const* d_in, const int* in_sizes, int n_in,
                              void* d_out, int out_size) {
    const float* x  = (const float*)d_in[0];
    const float* xb = (const float*)d_in[1];
    const float* w  = (const float*)d_in[2];
    const float* b  = (const float*)d_in[3];
    float* out = (float*)d_out;

    prep_kernel<<<512, 256>>>(x, xb, w);
    rbf_main_kernel<<<GRID_MAIN, 256>>>();
    finish_kernel<<<KROWS / 256, 256>>>(b, out);
}